// round 2
// baseline (speedup 1.0000x reference)
#include <cuda_runtime.h>
#include <math.h>

#define Bq 64
#define Sq 256
#define Tq 128
#define Hq 512
#define Eq 512
#define G4q 2048

// ---------------- scratch (static device memory; no allocations) ----------------
__device__ float g_xW[(size_t)Bq * Sq * G4q];     // 134 MB: x@W_ih^T + b_ih + b_hh, per (b,s)
__device__ float g_enc[(size_t)Bq * Sq * Hq];     // encoder hidden states, layout (b*S+s, h)
__device__ float g_encpart[(size_t)Bq * Sq * Hq]; // enc_outs @ W1_enc^T + b1
__device__ float g_qbuf[(size_t)Bq * Tq * Hq];    // dec_h @ W1_dec^T
__device__ float g_hA[Bq * Hq];
__device__ float g_hB[Bq * Hq];
__device__ float g_cst[Bq * Hq];

__device__ __forceinline__ float sigmoidf_(float x) { return 1.0f / (1.0f + expf(-x)); }

// ---------------- init h0/c0 broadcast ----------------
__global__ void init_state_kernel(const float* __restrict__ h0, const float* __restrict__ c0) {
    int i = blockIdx.x * blockDim.x + threadIdx.x;
    if (i < Bq * Hq) {
        g_hA[i] = h0[i % Hq];
        g_cst[i] = c0[i % Hq];
    }
}

// ---------------- generic fp32 GEMM:  C[m,n] = sum_k A[row(m),k] * Wt[n,k] + bias(+bias2) ----
// Tiles: BM=128, BN=64, BK=16, 256 threads, 8x4 thread tile.
// A row stride == K. Wt row stride == ldb. Optional row gather via rows[].
__global__ __launch_bounds__(256) void gemm_bias(
    const float* __restrict__ A, const float* __restrict__ Wt,
    const int* __restrict__ rows,
    const float* __restrict__ bias, const float* __restrict__ bias2,
    float* __restrict__ C, int K, int ldb, int ldc)
{
    __shared__ __align__(16) float As[16][128];
    __shared__ __align__(16) float Bs[16][64];

    int m0 = blockIdx.x * 128;
    int n0 = blockIdx.y * 64;
    int t  = threadIdx.x;
    int ty = t >> 4;       // 0..15 -> m = ty*8
    int tx = t & 15;       // 0..15 -> n = tx*4

    float acc[8][4];
#pragma unroll
    for (int i = 0; i < 8; i++)
#pragma unroll
        for (int j = 0; j < 4; j++) acc[i][j] = 0.0f;

    int am = t >> 1;              // 0..127
    int ak = (t & 1) * 8;         // 0 or 8
    long arow = rows ? (long)rows[m0 + am] : (long)(m0 + am);
    const float* Aptr = A + arow * (long)K + ak;

    int bn = t >> 2;              // 0..63
    int bk = (t & 3) * 4;         // 0,4,8,12
    const float* Bptr = Wt + (long)(n0 + bn) * ldb + bk;

    for (int k0 = 0; k0 < K; k0 += 16) {
        float4 a0 = *(const float4*)(Aptr + k0);
        float4 a1 = *(const float4*)(Aptr + k0 + 4);
        float4 bv = *(const float4*)(Bptr + k0);
        __syncthreads();
        As[ak + 0][am] = a0.x; As[ak + 1][am] = a0.y; As[ak + 2][am] = a0.z; As[ak + 3][am] = a0.w;
        As[ak + 4][am] = a1.x; As[ak + 5][am] = a1.y; As[ak + 6][am] = a1.z; As[ak + 7][am] = a1.w;
        Bs[bk + 0][bn] = bv.x; Bs[bk + 1][bn] = bv.y; Bs[bk + 2][bn] = bv.z; Bs[bk + 3][bn] = bv.w;
        __syncthreads();
#pragma unroll
        for (int kk = 0; kk < 16; ++kk) {
            float4 x0 = *(const float4*)&As[kk][ty * 8];
            float4 x1 = *(const float4*)&As[kk][ty * 8 + 4];
            float4 y  = *(const float4*)&Bs[kk][tx * 4];
            float av[8] = {x0.x, x0.y, x0.z, x0.w, x1.x, x1.y, x1.z, x1.w};
            float bw[4] = {y.x, y.y, y.z, y.w};
#pragma unroll
            for (int i = 0; i < 8; i++)
#pragma unroll
                for (int j = 0; j < 4; j++)
                    acc[i][j] = fmaf(av[i], bw[j], acc[i][j]);
        }
    }

    float bb[4];
#pragma unroll
    for (int j = 0; j < 4; j++) {
        int n = n0 + tx * 4 + j;
        float v = 0.0f;
        if (bias)  v += bias[n];
        if (bias2) v += bias2[n];
        bb[j] = v;
    }
#pragma unroll
    for (int i = 0; i < 8; i++) {
        long crow = (long)(m0 + ty * 8 + i) * ldc + n0 + tx * 4;
#pragma unroll
        for (int j = 0; j < 4; j++)
            C[crow + j] = acc[i][j] + bb[j];
    }
}

// ---------------- LSTM step:  g = extra + h @ Whh^T ; gates -> c,h ----------------
__global__ __launch_bounds__(128) void lstm_step(
    const float* __restrict__ hprev, float* __restrict__ hnext, float* __restrict__ cst,
    const float* __restrict__ Whh,
    const float* __restrict__ xW, long xstride,
    const float* __restrict__ dbih, const float* __restrict__ dbhh,
    float* __restrict__ hout, long hstride)
{
    __shared__ __align__(16) float hs[16][64];   // [k][m]
    __shared__ __align__(16) float ws[16][16];   // [k][nloc]

    int j0 = blockIdx.x * 4;
    int t  = threadIdx.x;
    int ty = t >> 3;   // 0..15 -> m = ty*4
    int tx = t & 7;    // 0..7  -> nloc = tx*2

    float acc[4][2];
#pragma unroll
    for (int i = 0; i < 4; i++) { acc[i][0] = 0.0f; acc[i][1] = 0.0f; }

    int am = t >> 1;            // 0..63
    int ak = (t & 1) * 8;       // 0 or 8
    const float* hp = hprev + (long)am * Hq + ak;

    int wn = t >> 3;            // 0..15 : nloc
    int wk = t & 7;             // 0..7
    int grow = (wn >> 2) * Hq + j0 + (wn & 3);   // gate = wn/4, jj = wn%4
    const float* wp = Whh + (long)grow * Hq + wk;

    for (int k0 = 0; k0 < Hq; k0 += 16) {
        float4 a0 = *(const float4*)(hp + k0);
        float4 a1 = *(const float4*)(hp + k0 + 4);
        float w0 = wp[k0];
        float w1 = wp[k0 + 8];
        __syncthreads();
        hs[ak + 0][am] = a0.x; hs[ak + 1][am] = a0.y; hs[ak + 2][am] = a0.z; hs[ak + 3][am] = a0.w;
        hs[ak + 4][am] = a1.x; hs[ak + 5][am] = a1.y; hs[ak + 6][am] = a1.z; hs[ak + 7][am] = a1.w;
        ws[wk][wn] = w0; ws[wk + 8][wn] = w1;
        __syncthreads();
#pragma unroll
        for (int kk = 0; kk < 16; ++kk) {
            float4 a = *(const float4*)&hs[kk][ty * 4];
            float2 bv = *(const float2*)&ws[kk][tx * 2];
            float av[4] = {a.x, a.y, a.z, a.w};
            float bw[2] = {bv.x, bv.y};
#pragma unroll
            for (int i = 0; i < 4; i++)
#pragma unroll
                for (int j = 0; j < 2; j++)
                    acc[i][j] = fmaf(av[i], bw[j], acc[i][j]);
        }
    }

    // exchange gate partials through smem (reuse hs)
    __syncthreads();
    float (*gsm)[64] = (float(*)[64])&hs[0][0];   // [nloc][m], nloc = gate*4 + jj
#pragma unroll
    for (int i = 0; i < 4; i++) {
        gsm[tx * 2 + 0][ty * 4 + i] = acc[i][0];
        gsm[tx * 2 + 1][ty * 4 + i] = acc[i][1];
    }
    __syncthreads();

#pragma unroll
    for (int r = 0; r < 2; r++) {
        int idx = t + r * 128;       // 0..255
        int m = idx & 63;
        int jj = idx >> 6;           // 0..3
        int j = j0 + jj;
        float vi = gsm[jj][m];
        float vf = gsm[4 + jj][m];
        float vg = gsm[8 + jj][m];
        float vo = gsm[12 + jj][m];
        if (xW) {
            const float* xr = xW + (long)m * xstride;
            vi += xr[j];
            vf += xr[Hq + j];
            vg += xr[2 * Hq + j];
            vo += xr[3 * Hq + j];
        } else {
            vi += dbih[j]          + dbhh[j];
            vf += dbih[Hq + j]     + dbhh[Hq + j];
            vg += dbih[2 * Hq + j] + dbhh[2 * Hq + j];
            vo += dbih[3 * Hq + j] + dbhh[3 * Hq + j];
        }
        float c_old = cst[m * Hq + j];
        float cn = sigmoidf_(vf) * c_old + sigmoidf_(vi) * tanhf(vg);
        float hn = sigmoidf_(vo) * tanhf(cn);
        cst[m * Hq + j] = cn;
        hnext[m * Hq + j] = hn;
        hout[(long)m * hstride + j] = hn;
    }
}

// ---------------- scoring: score[b,t,s] = b2 + sum_h W2[h]*relu(encpart[b,s,h]+q[b,t,h]) ----
__global__ __launch_bounds__(256) void score_kernel(
    const float* __restrict__ encpart, const float* __restrict__ q,
    const float* __restrict__ W2, const float* __restrict__ b2,
    float* __restrict__ out)
{
    __shared__ __align__(16) float qs[16][512];
    int b = blockIdx.y;
    int s0 = blockIdx.x * 16;
    int t = threadIdx.x;
    int warp = t >> 5;
    int lane = t & 31;

    float w2r[16], e0[16], e1[16];
    const float* ep = encpart + ((long)b * Sq + s0 + warp * 2) * Hq;
#pragma unroll
    for (int i = 0; i < 16; i++) {
        w2r[i] = W2[lane + 32 * i];
        e0[i] = ep[lane + 32 * i];
        e1[i] = ep[Hq + lane + 32 * i];
    }
    float b2v = b2[0];

    for (int tc = 0; tc < Tq / 16; ++tc) {
        __syncthreads();
        const float* qp = q + ((long)b * Tq + tc * 16) * Hq;
#pragma unroll
        for (int r = 0; r < 8; r++) {
            int lin = t + 256 * r;          // float4 slot 0..2047
            int tt = lin >> 7;
            int off = (lin & 127) * 4;
            *(float4*)&qs[tt][off] = *(const float4*)(qp + (long)tt * Hq + off);
        }
        __syncthreads();
#pragma unroll 4
        for (int tt = 0; tt < 16; ++tt) {
            float a0 = 0.0f, a1 = 0.0f;
#pragma unroll
            for (int i = 0; i < 16; i++) {
                float qv = qs[tt][lane + 32 * i];
                float v0 = fmaxf(e0[i] + qv, 0.0f);
                float v1 = fmaxf(e1[i] + qv, 0.0f);
                a0 = fmaf(v0, w2r[i], a0);
                a1 = fmaf(v1, w2r[i], a1);
            }
#pragma unroll
            for (int o = 16; o; o >>= 1) {
                a0 += __shfl_xor_sync(0xffffffffu, a0, o);
                a1 += __shfl_xor_sync(0xffffffffu, a1, o);
            }
            if (lane == 0) {
                long row = ((long)b * Tq + tc * 16 + tt) * Sq + s0 + warp * 2;
                out[row] = a0 + b2v;
                out[row + 1] = a1 + b2v;
            }
        }
    }
}

// ---------------- masked log_softmax over s (in place); mask is int32 (bool promoted) ----
__global__ __launch_bounds__(256) void lsm_kernel(float* __restrict__ io,
                                                  const int* __restrict__ mask)
{
    int row = blockIdx.x * 8 + (threadIdx.x >> 5);   // 0 .. B*T-1
    int lane = threadIdx.x & 31;
    int b = row / Tq;
    const int* mrow = mask + (long)b * Sq;
    float* x = io + (long)row * Sq;

    float v[8];
    float mx = -INFINITY;
#pragma unroll
    for (int i = 0; i < 8; i++) {
        int s = lane + 32 * i;
        float xv = x[s];
        v[i] = (mrow[s] != 0) ? xv : -INFINITY;
        mx = fmaxf(mx, v[i]);
    }
#pragma unroll
    for (int o = 16; o; o >>= 1) mx = fmaxf(mx, __shfl_xor_sync(0xffffffffu, mx, o));
    float sum = 0.0f;
#pragma unroll
    for (int i = 0; i < 8; i++) sum += expf(v[i] - mx);
#pragma unroll
    for (int o = 16; o; o >>= 1) sum += __shfl_xor_sync(0xffffffffu, sum, o);
    float lse = mx + logf(sum);
#pragma unroll
    for (int i = 0; i < 8; i++) {
        int s = lane + 32 * i;
        x[s] = v[i] - lse;
    }
}

// ---------------- launch ----------------
extern "C" void kernel_launch(void* const* d_in, const int* in_sizes, int n_in,
                              void* d_out, int out_size)
{
    const int*   state = (const int*)d_in[0];
    const int*   mask  = (const int*)d_in[1];
    // d_in[2] = max_decoding_length (compile-time T)
    const float* emb  = (const float*)d_in[3];
    const float* eWih = (const float*)d_in[4];
    const float* eWhh = (const float*)d_in[5];
    const float* ebih = (const float*)d_in[6];
    const float* ebhh = (const float*)d_in[7];
    const float* h0   = (const float*)d_in[8];
    const float* c0   = (const float*)d_in[9];
    // d_in[10] = dec_W_ih (input is zero -> unused)
    const float* dWhh = (const float*)d_in[11];
    const float* dbih = (const float*)d_in[12];
    const float* dbhh = (const float*)d_in[13];
    const float* W1   = (const float*)d_in[14];
    const float* b1   = (const float*)d_in[15];
    const float* W2   = (const float*)d_in[16];
    const float* b2   = (const float*)d_in[17];

    float* out_logits = (float*)d_out;
    float* out_dec    = out_logits + (size_t)Bq * Tq * Sq;

    float *xW, *enc, *encpart, *q, *hA, *hB, *cst;
    cudaGetSymbolAddress((void**)&xW, g_xW);
    cudaGetSymbolAddress((void**)&enc, g_enc);
    cudaGetSymbolAddress((void**)&encpart, g_encpart);
    cudaGetSymbolAddress((void**)&q, g_qbuf);
    cudaGetSymbolAddress((void**)&hA, g_hA);
    cudaGetSymbolAddress((void**)&hB, g_hB);
    cudaGetSymbolAddress((void**)&cst, g_cst);

    // 1. init h/c
    init_state_kernel<<<(Bq * Hq + 255) / 256, 256>>>(h0, c0);

    // 2. xW = emb[state] @ enc_W_ih^T + (b_ih + b_hh)
    gemm_bias<<<dim3((Bq * Sq) / 128, G4q / 64), 256>>>(
        emb, eWih, state, ebih, ebhh, xW, Eq, Eq, G4q);

    // 3. encoder recurrence (h double-buffered; c in-place)
    float* hbuf[2] = {hA, hB};
    for (int u = 0; u < Sq; ++u) {
        lstm_step<<<Hq / 4, 128>>>(hbuf[u & 1], hbuf[(u + 1) & 1], cst, eWhh,
                                   xW + (size_t)u * G4q, (long)Sq * G4q,
                                   nullptr, nullptr,
                                   enc + (size_t)u * Hq, (long)Sq * Hq);
    }

    // 4. enc_part = enc_outs @ W1_enc^T + b1     (W1 row stride = K+H = 1024)
    gemm_bias<<<dim3((Bq * Sq) / 128, Hq / 64), 256>>>(
        enc, W1, nullptr, b1, nullptr, encpart, Hq, Hq * 2, Hq);

    // 5. decoder recurrence (continues h/c; parity continues since S is even)
    for (int u = 0; u < Tq; ++u) {
        lstm_step<<<Hq / 4, 128>>>(hbuf[u & 1], hbuf[(u + 1) & 1], cst, dWhh,
                                   nullptr, 0,
                                   dbih, dbhh,
                                   out_dec + (size_t)u * Hq, (long)Tq * Hq);
    }

    // 6. q = dec_hs @ W1_dec^T
    gemm_bias<<<dim3((Bq * Tq) / 128, Hq / 64), 256>>>(
        out_dec, W1 + Hq, nullptr, nullptr, nullptr, q, Hq, Hq * 2, Hq);

    // 7. scores -> out_logits (raw)
    score_kernel<<<dim3(Sq / 16, Bq), 256>>>(encpart, q, W2, b2, out_logits);

    // 8. masked log_softmax in place
    lsm_kernel<<<(Bq * Tq) / 8, 256>>>(out_logits, mask);

    (void)in_sizes; (void)n_in; (void)out_size;
}

// round 4
// speedup vs baseline: 2.4822x; 2.4822x over previous
#include <cuda_runtime.h>
#include <math.h>

#define Bq 64
#define Sq 256
#define Tq 128
#define Hq 512
#define Eq 512
#define G4q 2048

typedef unsigned long long ull;

// ---------------- scratch (static device memory; no allocations) ----------------
__device__ float g_xW[(size_t)Bq * Sq * G4q];     // x@W_ih^T + b_ih + b_hh, per (b,s)
__device__ float g_enc[(size_t)Bq * Sq * Hq];     // encoder hidden states, layout (b*S+s, h)
__device__ float g_encpart[(size_t)Bq * Sq * Hq]; // enc_outs @ W1_enc^T + b1
__device__ float g_qbuf[(size_t)Bq * Tq * Hq];    // dec_h @ W1_dec^T
__device__ float g_hA[Bq * Hq];
__device__ float g_hB[Bq * Hq];
__device__ int   g_bar[4 * 384];                  // per m-group, per step arrival counters

__device__ __forceinline__ float sigmoidf_(float x) { return 1.0f / (1.0f + expf(-x)); }

__device__ __forceinline__ void fma2(ull& d, ull a, ull b) {
    asm("fma.rn.f32x2 %0, %1, %2, %0;" : "+l"(d) : "l"(a), "l"(b));
}
__device__ __forceinline__ float hsum2(ull a) {
    float lo = __uint_as_float((unsigned)(a & 0xffffffffu));
    float hi = __uint_as_float((unsigned)(a >> 32));
    return lo + hi;
}

// ---------------- init: broadcast h0 into hA; zero step barriers ----------------
__global__ void init_state_kernel(const float* __restrict__ h0) {
    int i = blockIdx.x * blockDim.x + threadIdx.x;
    if (i < Bq * Hq) g_hA[i] = h0[i & (Hq - 1)];
    int b = i - Bq * Hq;
    if (b >= 0 && b < 4 * 384) g_bar[b] = 0;
}

// ---------------- generic fp32 GEMM:  C[m,n] = sum_k A[row(m),k] * Wt[n,k] + bias(+bias2) ----
__global__ __launch_bounds__(256) void gemm_bias(
    const float* __restrict__ A, const float* __restrict__ Wt,
    const int* __restrict__ rows,
    const float* __restrict__ bias, const float* __restrict__ bias2,
    float* __restrict__ C, int K, int ldb, int ldc)
{
    __shared__ __align__(16) float As[16][128];
    __shared__ __align__(16) float Bs[16][64];

    int m0 = blockIdx.x * 128;
    int n0 = blockIdx.y * 64;
    int t  = threadIdx.x;
    int ty = t >> 4;
    int tx = t & 15;

    float acc[8][4];
#pragma unroll
    for (int i = 0; i < 8; i++)
#pragma unroll
        for (int j = 0; j < 4; j++) acc[i][j] = 0.0f;

    int am = t >> 1;
    int ak = (t & 1) * 8;
    long arow = rows ? (long)rows[m0 + am] : (long)(m0 + am);
    const float* Aptr = A + arow * (long)K + ak;

    int bn = t >> 2;
    int bk = (t & 3) * 4;
    const float* Bptr = Wt + (long)(n0 + bn) * ldb + bk;

    for (int k0 = 0; k0 < K; k0 += 16) {
        float4 a0 = *(const float4*)(Aptr + k0);
        float4 a1 = *(const float4*)(Aptr + k0 + 4);
        float4 bv = *(const float4*)(Bptr + k0);
        __syncthreads();
        As[ak + 0][am] = a0.x; As[ak + 1][am] = a0.y; As[ak + 2][am] = a0.z; As[ak + 3][am] = a0.w;
        As[ak + 4][am] = a1.x; As[ak + 5][am] = a1.y; As[ak + 6][am] = a1.z; As[ak + 7][am] = a1.w;
        Bs[bk + 0][bn] = bv.x; Bs[bk + 1][bn] = bv.y; Bs[bk + 2][bn] = bv.z; Bs[bk + 3][bn] = bv.w;
        __syncthreads();
#pragma unroll
        for (int kk = 0; kk < 16; ++kk) {
            float4 x0 = *(const float4*)&As[kk][ty * 8];
            float4 x1 = *(const float4*)&As[kk][ty * 8 + 4];
            float4 y  = *(const float4*)&Bs[kk][tx * 4];
            float av[8] = {x0.x, x0.y, x0.z, x0.w, x1.x, x1.y, x1.z, x1.w};
            float bw[4] = {y.x, y.y, y.z, y.w};
#pragma unroll
            for (int i = 0; i < 8; i++)
#pragma unroll
                for (int j = 0; j < 4; j++)
                    acc[i][j] = fmaf(av[i], bw[j], acc[i][j]);
        }
    }

    float bb[4];
#pragma unroll
    for (int j = 0; j < 4; j++) {
        int n = n0 + tx * 4 + j;
        float v = 0.0f;
        if (bias)  v += bias[n];
        if (bias2) v += bias2[n];
        bb[j] = v;
    }
#pragma unroll
    for (int i = 0; i < 8; i++) {
        long crow = (long)(m0 + ty * 8 + i) * ldc + n0 + tx * 4;
#pragma unroll
        for (int j = 0; j < 4; j++)
            C[crow + j] = acc[i][j] + bb[j];
    }
}

// ---------------- persistent fused LSTM recurrence (enc 256 + dec 128 steps) ----------
// Grid: 128 CTAs x 256 threads. CTA (mb, jb): m-block = 16 batches, j-slice = 16 cols.
// smem: ws[64][516] weight slice (4 gates x 16 j), hs[16][516] staged h, ex[64][17] gates.
#define WSTR 516
#define SMEM_PERS ((64 * WSTR + 16 * WSTR + 64 * 17) * 4)

__device__ __forceinline__ void load_wslice(float* ws, const float* __restrict__ W,
                                            int j0, int tid) {
    for (int idx = tid; idx < 64 * 128; idx += 256) {
        int r = idx >> 7;          // 0..63
        int k16 = idx & 127;       // float4 index
        int n = (r >> 4) * Hq + j0 + (r & 15);
        float4 v = *(const float4*)(W + (size_t)n * Hq + k16 * 4);
        *(float4*)(ws + r * WSTR + k16 * 4) = v;
    }
}

__global__ __launch_bounds__(256, 1) void lstm_persistent(
    const float* __restrict__ xW,
    const float* __restrict__ eWhh, const float* __restrict__ dWhh,
    const float* __restrict__ dbih, const float* __restrict__ dbhh,
    const float* __restrict__ c0,
    float* __restrict__ enc, float* __restrict__ dec_out)
{
    extern __shared__ float smem[];
    float* ws = smem;
    float* hs = smem + 64 * WSTR;
    float* ex = smem + 64 * WSTR + 16 * WSTR;

    int tid = threadIdx.x;
    int bx = blockIdx.x;
    int mb = bx >> 5;          // 0..3  (m-group)
    int jb = bx & 31;          // 0..31
    int j0 = jb * 16;

    // compute-role mapping
    int lane = tid & 31, wrp = tid >> 5;
    int ln3 = lane & 7, lm = lane >> 3;
    int r = wrp * 8 + ln3;                       // weight row 0..63 (= g*16 + jj)
    const ulonglong2* wrow = (const ulonglong2*)(ws + r * WSTR);
    const ulonglong2* h0p = (const ulonglong2*)(hs + (lm + 0) * WSTR);
    const ulonglong2* h1p = (const ulonglong2*)(hs + (lm + 4) * WSTR);
    const ulonglong2* h2p = (const ulonglong2*)(hs + (lm + 8) * WSTR);
    const ulonglong2* h3p = (const ulonglong2*)(hs + (lm + 12) * WSTR);

    // epilogue-role mapping
    int em = tid >> 4;         // 0..15 local m
    int ejj = tid & 15;        // 0..15 local j
    int j = j0 + ejj;
    int mg = mb * 16 + em;     // global batch index
    float c_reg = c0[j];
    float bi = 0.f, bf = 0.f, bg = 0.f, bo = 0.f;

    load_wslice(ws, eWhh, j0, tid);

    for (int step = 0; step < Sq + Tq; ++step) {
        const bool encp = (step < Sq);
        if (step == Sq) {
            __syncthreads();
            load_wslice(ws, dWhh, j0, tid);
            bi = dbih[j]           + dbhh[j];
            bf = dbih[Hq + j]      + dbhh[Hq + j];
            bg = dbih[2 * Hq + j]  + dbhh[2 * Hq + j];
            bo = dbih[3 * Hq + j]  + dbhh[3 * Hq + j];
        }
        const float* hcur = (step & 1) ? g_hB : g_hA;
        float*       hnxt = (step & 1) ? g_hA : g_hB;

        // stage this m-block's h rows into smem (FULL 512 floats per row: 2048 float4s)
        {
            const float* src = hcur + (size_t)mb * 16 * Hq;
#pragma unroll
            for (int rr = 0; rr < 8; ++rr) {
                int lin = tid + 256 * rr;     // float4 slot 0..2047
                int row = lin >> 7;           // 0..15
                int c4  = lin & 127;          // 0..127
                float4 v = *(const float4*)(src + (size_t)row * Hq + c4 * 4);
                *(float4*)(hs + row * WSTR + c4 * 4) = v;
            }
        }
        // prefetch the per-step additive term (xW for encoder, bias for decoder)
        float xw0, xw1, xw2, xw3;
        if (encp) {
            const float* xr = xW + ((size_t)mg * Sq + step) * G4q + j;
            xw0 = xr[0]; xw1 = xr[Hq]; xw2 = xr[2 * Hq]; xw3 = xr[3 * Hq];
        } else {
            xw0 = bi; xw1 = bf; xw2 = bg; xw3 = bo;
        }
        __syncthreads();

        // g(r, m) = sum_k ws[r][k] * hs[m][k] ; packed f32x2 over k-pairs
        ull a0 = 0, a1 = 0, a2 = 0, a3 = 0;
#pragma unroll 4
        for (int k4 = 0; k4 < 128; ++k4) {
            ulonglong2 wv = wrow[k4];
            ulonglong2 hv0 = h0p[k4];
            ulonglong2 hv1 = h1p[k4];
            ulonglong2 hv2 = h2p[k4];
            ulonglong2 hv3 = h3p[k4];
            fma2(a0, hv0.x, wv.x); fma2(a0, hv0.y, wv.y);
            fma2(a1, hv1.x, wv.x); fma2(a1, hv1.y, wv.y);
            fma2(a2, hv2.x, wv.x); fma2(a2, hv2.y, wv.y);
            fma2(a3, hv3.x, wv.x); fma2(a3, hv3.y, wv.y);
        }
        // exchange gate partials: ex[r][m]
        ex[r * 17 + (lm + 0)]  = hsum2(a0);
        ex[r * 17 + (lm + 4)]  = hsum2(a1);
        ex[r * 17 + (lm + 8)]  = hsum2(a2);
        ex[r * 17 + (lm + 12)] = hsum2(a3);
        __syncthreads();

        // epilogue: thread (em, ejj)
        float vi = ex[(0 * 16 + ejj) * 17 + em] + xw0;
        float vf = ex[(1 * 16 + ejj) * 17 + em] + xw1;
        float vg = ex[(2 * 16 + ejj) * 17 + em] + xw2;
        float vo = ex[(3 * 16 + ejj) * 17 + em] + xw3;
        float cn = sigmoidf_(vf) * c_reg + sigmoidf_(vi) * tanhf(vg);
        float hn = sigmoidf_(vo) * tanhf(cn);
        c_reg = cn;
        hnxt[(size_t)mg * Hq + j] = hn;
        if (encp) enc[((size_t)mg * Sq + step) * Hq + j] = hn;
        else      dec_out[((size_t)mg * Tq + (step - Sq)) * Hq + j] = hn;

        // group barrier (32 CTAs sharing this m-block)
        __syncthreads();
        if (tid == 0) {
            int* bar = &g_bar[mb * 384 + step];
            asm volatile("red.release.gpu.global.add.s32 [%0], 1;" :: "l"(bar) : "memory");
            int v;
            do {
                asm volatile("ld.acquire.gpu.global.b32 %0, [%1];" : "=r"(v) : "l"(bar) : "memory");
            } while (v < 32);
        }
        __syncthreads();
    }
}

// ---------------- scoring: score[b,t,s] = b2 + sum_h W2[h]*relu(encpart[b,s,h]+q[b,t,h]) ----
__global__ __launch_bounds__(256) void score_kernel(
    const float* __restrict__ encpart, const float* __restrict__ q,
    const float* __restrict__ W2, const float* __restrict__ b2,
    float* __restrict__ out)
{
    __shared__ __align__(16) float qs[16][512];
    int b = blockIdx.y;
    int s0 = blockIdx.x * 16;
    int t = threadIdx.x;
    int warp = t >> 5;
    int lane = t & 31;

    float w2r[16], e0[16], e1[16];
    const float* ep = encpart + ((long)b * Sq + s0 + warp * 2) * Hq;
#pragma unroll
    for (int i = 0; i < 16; i++) {
        w2r[i] = W2[lane + 32 * i];
        e0[i] = ep[lane + 32 * i];
        e1[i] = ep[Hq + lane + 32 * i];
    }
    float b2v = b2[0];

    for (int tc = 0; tc < Tq / 16; ++tc) {
        __syncthreads();
        const float* qp = q + ((long)b * Tq + tc * 16) * Hq;
#pragma unroll
        for (int rr = 0; rr < 8; rr++) {
            int lin = t + 256 * rr;
            int tt = lin >> 7;
            int off = (lin & 127) * 4;
            *(float4*)&qs[tt][off] = *(const float4*)(qp + (long)tt * Hq + off);
        }
        __syncthreads();
#pragma unroll 4
        for (int tt = 0; tt < 16; ++tt) {
            float a0 = 0.0f, a1 = 0.0f;
#pragma unroll
            for (int i = 0; i < 16; i++) {
                float qv = qs[tt][lane + 32 * i];
                float v0 = fmaxf(e0[i] + qv, 0.0f);
                float v1 = fmaxf(e1[i] + qv, 0.0f);
                a0 = fmaf(v0, w2r[i], a0);
                a1 = fmaf(v1, w2r[i], a1);
            }
#pragma unroll
            for (int o = 16; o; o >>= 1) {
                a0 += __shfl_xor_sync(0xffffffffu, a0, o);
                a1 += __shfl_xor_sync(0xffffffffu, a1, o);
            }
            if (lane == 0) {
                long row = ((long)b * Tq + tc * 16 + tt) * Sq + s0 + warp * 2;
                out[row] = a0 + b2v;
                out[row + 1] = a1 + b2v;
            }
        }
    }
}

// ---------------- masked log_softmax over s (in place); mask is int32 ----------------
__global__ __launch_bounds__(256) void lsm_kernel(float* __restrict__ io,
                                                  const int* __restrict__ mask)
{
    int row = blockIdx.x * 8 + (threadIdx.x >> 5);
    int lane = threadIdx.x & 31;
    int b = row / Tq;
    const int* mrow = mask + (long)b * Sq;
    float* x = io + (long)row * Sq;

    float v[8];
    float mx = -INFINITY;
#pragma unroll
    for (int i = 0; i < 8; i++) {
        int s = lane + 32 * i;
        float xv = x[s];
        v[i] = (mrow[s] != 0) ? xv : -INFINITY;
        mx = fmaxf(mx, v[i]);
    }
#pragma unroll
    for (int o = 16; o; o >>= 1) mx = fmaxf(mx, __shfl_xor_sync(0xffffffffu, mx, o));
    float sum = 0.0f;
#pragma unroll
    for (int i = 0; i < 8; i++) sum += expf(v[i] - mx);
#pragma unroll
    for (int o = 16; o; o >>= 1) sum += __shfl_xor_sync(0xffffffffu, sum, o);
    float lse = mx + logf(sum);
#pragma unroll
    for (int i = 0; i < 8; i++) {
        int s = lane + 32 * i;
        x[s] = v[i] - lse;
    }
}

// ---------------- launch ----------------
extern "C" void kernel_launch(void* const* d_in, const int* in_sizes, int n_in,
                              void* d_out, int out_size)
{
    const int*   state = (const int*)d_in[0];
    const int*   mask  = (const int*)d_in[1];
    const float* emb  = (const float*)d_in[3];
    const float* eWih = (const float*)d_in[4];
    const float* eWhh = (const float*)d_in[5];
    const float* ebih = (const float*)d_in[6];
    const float* ebhh = (const float*)d_in[7];
    const float* h0   = (const float*)d_in[8];
    const float* c0   = (const float*)d_in[9];
    const float* dWhh = (const float*)d_in[11];
    const float* dbih = (const float*)d_in[12];
    const float* dbhh = (const float*)d_in[13];
    const float* W1   = (const float*)d_in[14];
    const float* b1   = (const float*)d_in[15];
    const float* W2   = (const float*)d_in[16];
    const float* b2   = (const float*)d_in[17];

    float* out_logits = (float*)d_out;
    float* out_dec    = out_logits + (size_t)Bq * Tq * Sq;

    float *xW, *enc, *encpart, *q;
    cudaGetSymbolAddress((void**)&xW, g_xW);
    cudaGetSymbolAddress((void**)&enc, g_enc);
    cudaGetSymbolAddress((void**)&encpart, g_encpart);
    cudaGetSymbolAddress((void**)&q, g_qbuf);

    static int smem_set = 0;
    if (!smem_set) {
        cudaFuncSetAttribute(lstm_persistent,
                             cudaFuncAttributeMaxDynamicSharedMemorySize, SMEM_PERS);
        smem_set = 1;
    }

    // 1. init h (broadcast) + zero barriers
    init_state_kernel<<<(Bq * Hq + 4 * 384 + 255) / 256, 256>>>(h0);

    // 2. xW = emb[state] @ enc_W_ih^T + (b_ih + b_hh)
    gemm_bias<<<dim3((Bq * Sq) / 128, G4q / 64), 256>>>(
        emb, eWih, state, ebih, ebhh, xW, Eq, Eq, G4q);

    // 3+5. full recurrence (256 encoder + 128 decoder steps) in one persistent kernel
    lstm_persistent<<<128, 256, SMEM_PERS>>>(xW, eWhh, dWhh, dbih, dbhh, c0,
                                             enc, out_dec);

    // 4. enc_part = enc_outs @ W1_enc^T + b1   (W1 row stride = 1024)
    gemm_bias<<<dim3((Bq * Sq) / 128, Hq / 64), 256>>>(
        enc, W1, nullptr, b1, nullptr, encpart, Hq, Hq * 2, Hq);

    // 6. q = dec_hs @ W1_dec^T
    gemm_bias<<<dim3((Bq * Tq) / 128, Hq / 64), 256>>>(
        out_dec, W1 + Hq, nullptr, nullptr, nullptr, q, Hq, Hq * 2, Hq);

    // 7. scores -> out_logits (raw)
    score_kernel<<<dim3(Sq / 16, Bq), 256>>>(encpart, q, W2, b2, out_logits);

    // 8. masked log_softmax in place
    lsm_kernel<<<(Bq * Tq) / 8, 256>>>(out_logits, mask);

    (void)in_sizes; (void)n_in; (void)out_size; (void)state;
}